// round 16
// baseline (speedup 1.0000x reference)
#include <cuda_runtime.h>
#include <cuda_bf16.h>
#include <math.h>
#include <stdint.h>

// Problem constants
#define BB 2
#define SS 2048
#define DD 768
#define HH 12
#define DK 64
#define QROWS 8
#define JTILE 64
#define SSTR 2072          // score strip stride (fp32 words)
#define KST 72             // K tile smem stride (bf16)
#define VSTN 72            // V^T tile smem stride (bf16)
#define QSB 72             // Q smem stride (bf16)
#define ATHREADS 256
#define STAGE_E (64*KST*2) // bf16 elems per stage (hi+lo)

#define OUT_MAIN (2LL*2048*768)
#define ATTN_ELEMS (2LL*12*2048*2048)

#define MROWS (BB*SS)            // 4096
#define ASEG ((size_t)MROWS*DD)  // 3145728
#define WSEG ((size_t)DD*DD)     // 589824

// scratch
__device__ float g_attn[(size_t)ATTN_ELEMS];
__device__ __nv_bfloat16 g_Ahi[3*ASEG];
__device__ __nv_bfloat16 g_Alo[3*ASEG];
__device__ __nv_bfloat16 g_Whi[4*WSEG];
__device__ __nv_bfloat16 g_Wlo[4*WSEG];
__device__ __nv_bfloat16 g_Qhi[ASEG], g_Qlo[ASEG];
__device__ __nv_bfloat16 g_Khi[ASEG], g_Klo[ASEG];
__device__ __nv_bfloat16 g_Vhi[ASEG], g_Vlo[ASEG];
__device__ __nv_bfloat16 g_Vthi[ASEG], g_Vtlo[ASEG];
__device__ __nv_bfloat16 g_Chi[ASEG], g_Clo[ASEG];

// ===================== helpers ==============================================
__device__ __forceinline__ void split2(float a, float b, uint32_t& hi, uint32_t& lo) {
    __nv_bfloat162 h = __floats2bfloat162_rn(a, b);
    float la = a - __bfloat162float(__low2bfloat16(h));
    float lb = b - __bfloat162float(__high2bfloat16(h));
    __nv_bfloat162 l = __floats2bfloat162_rn(la, lb);
    hi = *(uint32_t*)&h;
    lo = *(uint32_t*)&l;
}

__device__ __forceinline__ void mma_bf16(float* c, const uint32_t* a,
                                         uint32_t b0, uint32_t b1) {
    asm volatile(
        "mma.sync.aligned.m16n8k16.row.col.f32.bf16.bf16.f32 "
        "{%0,%1,%2,%3}, {%4,%5,%6,%7}, {%8,%9}, {%0,%1,%2,%3};"
        : "+f"(c[0]), "+f"(c[1]), "+f"(c[2]), "+f"(c[3])
        : "r"(a[0]), "r"(a[1]), "r"(a[2]), "r"(a[3]), "r"(b0), "r"(b1));
}

__device__ __forceinline__ uint32_t smem_u32(const void* p) {
    return (uint32_t)__cvta_generic_to_shared(p);
}
#define CP16(dst, src) \
    asm volatile("cp.async.cg.shared.global [%0], [%1], 16;" \
                 :: "r"(dst), "l"(src) : "memory")
#define CPCOMMIT() asm volatile("cp.async.commit_group;" ::: "memory")
#define CPWAIT(n)  asm volatile("cp.async.wait_group %0;" :: "n"(n) : "memory")

// ===================== fp32 -> bf16 hi/lo split (7 segments) ================
__global__ void cvt_all(const float* __restrict__ x0, const float* __restrict__ x1,
                        const float* __restrict__ x2,
                        const float* __restrict__ w0, const float* __restrict__ w1,
                        const float* __restrict__ w2, const float* __restrict__ w3,
                        __nv_bfloat16* __restrict__ ahi, __nv_bfloat16* __restrict__ alo,
                        __nv_bfloat16* __restrict__ whi, __nv_bfloat16* __restrict__ wlo,
                        int n4a, int n4w) {
    const int z = blockIdx.z;
    const float* x;
    __nv_bfloat16 *hi, *lo;
    int n4;
    if (z < 3) {
        x = (z == 0) ? x0 : (z == 1) ? x1 : x2;
        hi = ahi + (size_t)z * (size_t)n4a * 4;
        lo = alo + (size_t)z * (size_t)n4a * 4;
        n4 = n4a;
    } else {
        const int w = z - 3;
        x = (w == 0) ? w0 : (w == 1) ? w1 : (w == 2) ? w2 : w3;
        hi = whi + (size_t)w * (size_t)n4w * 4;
        lo = wlo + (size_t)w * (size_t)n4w * 4;
        n4 = n4w;
    }
    int i = blockIdx.x * blockDim.x + threadIdx.x;
    if (i >= n4) return;
    float4 v = ((const float4*)x)[i];
    uint32_t h01, l01, h23, l23;
    split2(v.x, v.y, h01, l01);
    split2(v.z, v.w, h23, l23);
    ((uint32_t*)hi)[i*2]     = h01;
    ((uint32_t*)hi)[i*2 + 1] = h23;
    ((uint32_t*)lo)[i*2]     = l01;
    ((uint32_t*)lo)[i*2 + 1] = l23;
}

// ===================== shared GEMM core (cp.async 2-stage) ==================
#define TST 40
#define GST_E (128*TST)

__device__ __forceinline__ void gemm_core(
        const __nv_bfloat16* __restrict__ Ah, const __nv_bfloat16* __restrict__ Al,
        const __nv_bfloat16* __restrict__ Wh, const __nv_bfloat16* __restrict__ Wl,
        int bm, int bn, float acc[2][8][4]) {
    __shared__ __nv_bfloat16 sbuf[2][4][GST_E];

    const int tid  = threadIdx.x;
    const int lane = tid & 31;
    const int wid  = tid >> 5;
    const int wm   = wid >> 1;
    const int wn   = wid & 1;
    const int g    = lane >> 2;
    const int tg   = lane & 3;

    const int lr = tid >> 2;
    const int lc = (tid & 3) * 8;

    const __nv_bfloat16* gsrc[4];
    gsrc[0] = Ah + (size_t)bm * DD;
    gsrc[1] = Al + (size_t)bm * DD;
    gsrc[2] = Wh + (size_t)bn * DD;
    gsrc[3] = Wl + (size_t)bn * DD;

    auto issue = [&](int st, int k0) {
#pragma unroll
        for (int a = 0; a < 4; a++) {
            const __nv_bfloat16* gp = gsrc[a] + k0 + lc;
            __nv_bfloat16* sp = sbuf[st][a];
            CP16(smem_u32(sp + lr * TST + lc),        gp + (size_t)lr * DD);
            CP16(smem_u32(sp + (lr + 64) * TST + lc), gp + (size_t)(lr + 64) * DD);
        }
    };

    issue(0, 0);
    CPCOMMIT();

    for (int k0 = 0; k0 < DD; k0 += 32) {
        const int st = (k0 >> 5) & 1;
        if (k0 + 32 < DD) { issue(st ^ 1, k0 + 32); CPCOMMIT(); CPWAIT(1); }
        else              { CPWAIT(0); }
        __syncthreads();

        const __nv_bfloat16* sAh = sbuf[st][0];
        const __nv_bfloat16* sAl = sbuf[st][1];
        const __nv_bfloat16* sWh = sbuf[st][2];
        const __nv_bfloat16* sWl = sbuf[st][3];

#pragma unroll
        for (int kk = 0; kk < 32; kk += 16) {
            uint32_t ah[2][4], al[2][4];
#pragma unroll
            for (int mi = 0; mi < 2; mi++) {
                const int ar = wm*32 + mi*16;
                ah[mi][0] = *(const uint32_t*)(sAh + (ar+g)   * TST + kk + tg*2);
                ah[mi][1] = *(const uint32_t*)(sAh + (ar+g+8) * TST + kk + tg*2);
                ah[mi][2] = *(const uint32_t*)(sAh + (ar+g)   * TST + kk + tg*2 + 8);
                ah[mi][3] = *(const uint32_t*)(sAh + (ar+g+8) * TST + kk + tg*2 + 8);
                al[mi][0] = *(const uint32_t*)(sAl + (ar+g)   * TST + kk + tg*2);
                al[mi][1] = *(const uint32_t*)(sAl + (ar+g+8) * TST + kk + tg*2);
                al[mi][2] = *(const uint32_t*)(sAl + (ar+g)   * TST + kk + tg*2 + 8);
                al[mi][3] = *(const uint32_t*)(sAl + (ar+g+8) * TST + kk + tg*2 + 8);
            }
            uint32_t bh[8][2], bl[8][2];
#pragma unroll
            for (int ni = 0; ni < 8; ni++) {
                const int nr = wn*64 + ni*8 + g;
                bh[ni][0] = *(const uint32_t*)(sWh + nr * TST + kk + tg*2);
                bh[ni][1] = *(const uint32_t*)(sWh + nr * TST + kk + tg*2 + 8);
                bl[ni][0] = *(const uint32_t*)(sWl + nr * TST + kk + tg*2);
                bl[ni][1] = *(const uint32_t*)(sWl + nr * TST + kk + tg*2 + 8);
            }
#pragma unroll
            for (int ni = 0; ni < 8; ni++)
#pragma unroll
                for (int mi = 0; mi < 2; mi++)
                    mma_bf16(acc[mi][ni], ah[mi], bh[ni][0], bh[ni][1]);
#pragma unroll
            for (int ni = 0; ni < 8; ni++)
#pragma unroll
                for (int mi = 0; mi < 2; mi++)
                    mma_bf16(acc[mi][ni], ah[mi], bl[ni][0], bl[ni][1]);
#pragma unroll
            for (int ni = 0; ni < 8; ni++)
#pragma unroll
                for (int mi = 0; mi < 2; mi++)
                    mma_bf16(acc[mi][ni], al[mi], bh[ni][0], bh[ni][1]);
        }
        __syncthreads();
    }
}

__global__ __launch_bounds__(256) void gemm_qkv(
        const __nv_bfloat16* __restrict__ Ahi, const __nv_bfloat16* __restrict__ Alo,
        const __nv_bfloat16* __restrict__ Whi, const __nv_bfloat16* __restrict__ Wlo,
        __nv_bfloat16* H0, __nv_bfloat16* L0,
        __nv_bfloat16* H1, __nv_bfloat16* L1,
        __nv_bfloat16* H2, __nv_bfloat16* L2) {
    const int z = blockIdx.z;
    const __nv_bfloat16* Ah = Ahi + (size_t)z * ASEG;
    const __nv_bfloat16* Al = Alo + (size_t)z * ASEG;
    const __nv_bfloat16* Wh = Whi + (size_t)z * WSEG;
    const __nv_bfloat16* Wl = Wlo + (size_t)z * WSEG;
    __nv_bfloat16* Ho = (z == 0) ? H0 : (z == 1) ? H1 : H2;
    __nv_bfloat16* Lo = (z == 0) ? L0 : (z == 1) ? L1 : L2;
    const int bm = blockIdx.y * 128, bn = blockIdx.x * 128;

    float acc[2][8][4];
#pragma unroll
    for (int mi = 0; mi < 2; mi++)
#pragma unroll
        for (int ni = 0; ni < 8; ni++)
#pragma unroll
            for (int r = 0; r < 4; r++) acc[mi][ni][r] = 0.f;

    gemm_core(Ah, Al, Wh, Wl, bm, bn, acc);

    const int lane = threadIdx.x & 31;
    const int wid  = threadIdx.x >> 5;
    const int wm = wid >> 1, wn = wid & 1;
    const int g = lane >> 2, tg = lane & 3;
#pragma unroll
    for (int mi = 0; mi < 2; mi++) {
        const int row0 = bm + wm*32 + mi*16 + g;
#pragma unroll
        for (int ni = 0; ni < 8; ni++) {
            const int col = bn + wn*64 + ni*8 + tg*2;
            uint32_t h0, l0, h1, l1;
            split2(acc[mi][ni][0], acc[mi][ni][1], h0, l0);
            split2(acc[mi][ni][2], acc[mi][ni][3], h1, l1);
            *(uint32_t*)(Ho + (size_t)row0 * DD + col)     = h0;
            *(uint32_t*)(Lo + (size_t)row0 * DD + col)     = l0;
            *(uint32_t*)(Ho + (size_t)(row0+8) * DD + col) = h1;
            *(uint32_t*)(Lo + (size_t)(row0+8) * DD + col) = l1;
        }
    }
}

__global__ __launch_bounds__(256) void gemm_out(
        const __nv_bfloat16* __restrict__ Ahi, const __nv_bfloat16* __restrict__ Alo,
        const __nv_bfloat16* __restrict__ Whi, const __nv_bfloat16* __restrict__ Wlo,
        const float* __restrict__ bias, float* __restrict__ C) {
    const int bm = blockIdx.y * 128, bn = blockIdx.x * 128;
    float acc[2][8][4];
#pragma unroll
    for (int mi = 0; mi < 2; mi++)
#pragma unroll
        for (int ni = 0; ni < 8; ni++)
#pragma unroll
            for (int r = 0; r < 4; r++) acc[mi][ni][r] = 0.f;

    gemm_core(Ahi, Alo, Whi, Wlo, bm, bn, acc);

    const int lane = threadIdx.x & 31;
    const int wid  = threadIdx.x >> 5;
    const int wm = wid >> 1, wn = wid & 1;
    const int g = lane >> 2, tg = lane & 3;
#pragma unroll
    for (int mi = 0; mi < 2; mi++) {
        const int row0 = bm + wm*32 + mi*16 + g;
#pragma unroll
        for (int ni = 0; ni < 8; ni++) {
            const int col = bn + wn*64 + ni*8 + tg*2;
            float b0v = bias[col], b1v = bias[col+1];
            float2 v0 = {acc[mi][ni][0] + b0v, acc[mi][ni][1] + b1v};
            float2 v1 = {acc[mi][ni][2] + b0v, acc[mi][ni][3] + b1v};
            *(float2*)(C + (size_t)row0 * DD + col)     = v0;
            *(float2*)(C + (size_t)(row0+8) * DD + col) = v1;
        }
    }
}

// ===================== V transpose: [b,s][h,d] -> [b,h][d][s] ==============
__global__ void transpose_v(const __nv_bfloat16* __restrict__ Vhi,
                            const __nv_bfloat16* __restrict__ Vlo,
                            __nv_bfloat16* __restrict__ Vthi,
                            __nv_bfloat16* __restrict__ Vtlo) {
    __shared__ uint16_t th[32][33], tl[32][33];
    const int b = blockIdx.z / HH, h = blockIdx.z % HH;
    const int s0 = blockIdx.x * 32, d0 = blockIdx.y * 32;
    const int tx = threadIdx.x, ty = threadIdx.y;
#pragma unroll
    for (int i = 0; i < 4; i++) {
        const int srow = ty + i * 8;
        const size_t gi = (size_t)(b * SS + s0 + srow) * DD + h * DK + d0 + tx;
        th[srow][tx] = ((const uint16_t*)Vhi)[gi];
        tl[srow][tx] = ((const uint16_t*)Vlo)[gi];
    }
    __syncthreads();
#pragma unroll
    for (int i = 0; i < 4; i++) {
        const int drow = ty + i * 8;
        const size_t go = ((size_t)(b * HH + h) * DK + d0 + drow) * SS + s0 + tx;
        ((uint16_t*)Vthi)[go] = th[tx][drow];
        ((uint16_t*)Vtlo)[go] = tl[tx][drow];
    }
}

// ===================== fused attention: QROWS=8, 2 blocks/SM ================
__global__ __launch_bounds__(ATHREADS, 2) void fused_attn(
        const __nv_bfloat16* __restrict__ Qhi, const __nv_bfloat16* __restrict__ Qlo,
        const __nv_bfloat16* __restrict__ Khi, const __nv_bfloat16* __restrict__ Klo,
        const __nv_bfloat16* __restrict__ Vthi, const __nv_bfloat16* __restrict__ Vtlo,
        float* __restrict__ attn,
        __nv_bfloat16* __restrict__ Chi, __nv_bfloat16* __restrict__ Clo) {
    const int qt = gridDim.x - 1 - blockIdx.x;
    const int h  = blockIdx.y;
    const int b  = blockIdx.z;
    const int q0 = qt * QROWS;
    const int tid = threadIdx.x;
    const int wid  = tid >> 5;      // 0..7
    const int lane = tid & 31;
    const int g    = lane >> 2;
    const int tg   = lane & 3;

    extern __shared__ float sm[];
    float* s = sm;                                                 // [8][SSTR]
    __nv_bfloat16* kbuf = (__nv_bfloat16*)(sm + QROWS * SSTR);     // 2 stages
    __nv_bfloat16* qsh = kbuf + 2 * STAGE_E;                      // 16*QSB
    __nv_bfloat16* qsl = qsh + 16 * QSB;                          // 16*QSB
    float* lrow = (float*)(qsl + 16 * QSB);                       // [8]
    float* wsum = lrow + 8;                                       // [8][8]

    // stage Q: rows 0..7 real, rows 8..15 zero (for m16 fragment reads)
    if (tid < 128) {
        const int r = tid >> 3, c8 = (tid & 7) * 8;
        if (r < QROWS) {
            const size_t gi = (size_t)(b * SS + q0 + r) * DD + h * DK + c8;
            *(uint4*)(qsh + r * QSB + c8) = *(const uint4*)(Qhi + gi);
            *(uint4*)(qsl + r * QSB + c8) = *(const uint4*)(Qlo + gi);
        } else {
            const uint4 z = {0, 0, 0, 0};
            *(uint4*)(qsh + r * QSB + c8) = z;
            *(uint4*)(qsl + r * QSB + c8) = z;
        }
    }
    __syncthreads();

    uint32_t qh[4][4], ql[4][4];
#pragma unroll
    for (int ks = 0; ks < 4; ks++) {
        const int c0 = ks * 16 + tg * 2;
        qh[ks][0] = *(const uint32_t*)(qsh + g * QSB + c0);
        qh[ks][1] = *(const uint32_t*)(qsh + (g + 8) * QSB + c0);
        qh[ks][2] = *(const uint32_t*)(qsh + g * QSB + c0 + 8);
        qh[ks][3] = *(const uint32_t*)(qsh + (g + 8) * QSB + c0 + 8);
        ql[ks][0] = *(const uint32_t*)(qsl + g * QSB + c0);
        ql[ks][1] = *(const uint32_t*)(qsl + (g + 8) * QSB + c0);
        ql[ks][2] = *(const uint32_t*)(qsl + g * QSB + c0 + 8);
        ql[ks][3] = *(const uint32_t*)(qsl + (g + 8) * QSB + c0 + 8);
    }

    const int ntile = (q0 + QROWS + JTILE - 1) / JTILE;
    const int jlim  = ntile * JTILE;

    // ---- Phase 1: S = QK^T (m16 q x n8 j), exp inline, row sums ----
    float rs0 = 0.f;
    {
        auto issueK = [&](int st, int t) {
            const int j0 = t * JTILE;
            __nv_bfloat16* kh = kbuf + st * STAGE_E;
            __nv_bfloat16* kl = kh + 64 * KST;
#pragma unroll
            for (int it = 0; it < 2; it++) {
                const int l = tid + it * ATHREADS;    // 0..511
                const int jr = l >> 3, c8 = (l & 7) * 8;
                const size_t gi = (size_t)(b * SS + j0 + jr) * DD + h * DK + c8;
                CP16(smem_u32(kh + jr * KST + c8), Khi + gi);
                CP16(smem_u32(kl + jr * KST + c8), Klo + gi);
            }
        };

        issueK(0, 0);
        CPCOMMIT();
        for (int t = 0; t < ntile; t++) {
            if (t + 1 < ntile) { issueK((t + 1) & 1, t + 1); CPCOMMIT(); CPWAIT(1); }
            else               { CPWAIT(0); }
            __syncthreads();

            const __nv_bfloat16* kh = kbuf + (t & 1) * STAGE_E;
            const __nv_bfloat16* kl = kh + 64 * KST;
            const int j0 = t * JTILE;
            const int n0 = wid * 8;                  // 8 warps x 8 j = 64
            float c[4] = {0.f, 0.f, 0.f, 0.f};
#pragma unroll
            for (int ks = 0; ks < 4; ks++) {
                const int ko = ks * 16 + tg * 2;
                uint32_t bh0 = *(const uint32_t*)(kh + (n0 + g) * KST + ko);
                uint32_t bh1 = *(const uint32_t*)(kh + (n0 + g) * KST + ko + 8);
                uint32_t bl0 = *(const uint32_t*)(kl + (n0 + g) * KST + ko);
                uint32_t bl1 = *(const uint32_t*)(kl + (n0 + g) * KST + ko + 8);
                mma_bf16(c, qh[ks], bh0, bh1);
                mma_bf16(c, qh[ks], bl0, bl1);
                mma_bf16(c, ql[ks], bh0, bh1);
            }
            const int gj = j0 + n0 + tg * 2;
            const int r0 = q0 + g;                   // valid q row
            float e00 = (gj     <= r0) ? __expf(c[0] * 0.125f) : 0.f;
            float e01 = (gj + 1 <= r0) ? __expf(c[1] * 0.125f) : 0.f;
            *(float2*)(s + g * SSTR + gj) = make_float2(e00, e01);
            rs0 += e00 + e01;
            __syncthreads();
        }
    }

    // ---- Phase 2: row-sum reduce ----
    rs0 += __shfl_xor_sync(0xffffffffu, rs0, 1);
    rs0 += __shfl_xor_sync(0xffffffffu, rs0, 2);
    if (tg == 0) wsum[wid * 8 + g] = rs0;
    __syncthreads();
    if (tid < 8) {
        float sum = 0.f;
#pragma unroll
        for (int w = 0; w < 8; w++) sum += wsum[w * 8 + tid];
        lrow[tid] = 1.0f / sum;
    }
    __syncthreads();

    // ---- Phase 3: zero-fill tail (j >= jlim) ----
    if (attn) {
        const float4 zz = {0.f, 0.f, 0.f, 0.f};
        const int jlim4 = jlim >> 2;
        for (int r = 0; r < QROWS; r++) {
            float4* arow = (float4*)(attn +
                (((size_t)(b * HH + h) * SS) + q0 + r) * SS);
            for (int j = jlim4 + tid; j < SS/4; j += ATHREADS)
                __stcs(&arow[j], zz);
        }
    }

    // ---- Phase 4: O^T = V^T P^T (m16 d x n8 q), fused weight write ----
    {
        const size_t vtbase = (size_t)(b * HH + h) * DK * SS;
        const size_t abase  = ((size_t)(b * HH + h) * SS + q0) * SS;
        auto issueV = [&](int st, int t) {
            const int j0 = t * JTILE;
            __nv_bfloat16* vh = kbuf + st * STAGE_E;
            __nv_bfloat16* vl = vh + 64 * VSTN;
#pragma unroll
            for (int it = 0; it < 2; it++) {
                const int l = tid + it * ATHREADS;
                const int d = l >> 3, j8 = (l & 7) * 8;
                const size_t gi = vtbase + (size_t)d * SS + j0 + j8;
                CP16(smem_u32(vh + d * VSTN + j8), Vthi + gi);
                CP16(smem_u32(vl + d * VSTN + j8), Vtlo + gi);
            }
        };

        const int dc = wid & 3;     // d-chunk (m16): d = dc*16 + [0..15]
        const int jh = wid >> 2;    // j-half: chunks {jh*2, jh*2+1}
        const float invg = lrow[g]; // this thread's weight-row scale (q = g)

        float acc[4] = {0.f, 0.f, 0.f, 0.f};

        issueV(0, 0);
        CPCOMMIT();
        for (int t = 0; t < ntile; t++) {
            if (t + 1 < ntile) { issueV((t + 1) & 1, t + 1); CPCOMMIT(); CPWAIT(1); }
            else               { CPWAIT(0); }
            __syncthreads();

            const __nv_bfloat16* vh = kbuf + (t & 1) * STAGE_E;
            const __nv_bfloat16* vl = vh + 64 * VSTN;
            const int j0 = t * JTILE;

#pragma unroll
            for (int jj = 0; jj < 2; jj++) {
                const int jc = jh * 2 + jj;          // k16 j-chunk 0..3
                const int jb = j0 + jc * 16;

                // P fragments (b): rows q=g, j = jb + tg*2(+1), +8(+9)
                float2 pA = *(const float2*)&s[g * SSTR + jb + tg * 2];
                float2 pB = *(const float2*)&s[g * SSTR + jb + tg * 2 + 8];

                // fused weight write (dc==0 warps own each j-chunk once)
                if (attn && dc == 0) {
                    __stcs((float2*)(attn + abase + (size_t)g * SS + jb + tg * 2),
                           make_float2(pA.x * invg, pA.y * invg));
                    __stcs((float2*)(attn + abase + (size_t)g * SS + jb + tg * 2 + 8),
                           make_float2(pB.x * invg, pB.y * invg));
                }

                uint32_t bh0, bl0, bh1, bl1;
                split2(pA.x, pA.y, bh0, bl0);
                split2(pB.x, pB.y, bh1, bl1);

                // V^T fragments (a): rows d = dc*16 + g, g+8; cols j
                const int jloc = jc * 16 + tg * 2;
                uint32_t ah[4], al[4];
                ah[0] = *(const uint32_t*)(vh + (dc*16 + g)     * VSTN + jloc);
                ah[1] = *(const uint32_t*)(vh + (dc*16 + g + 8) * VSTN + jloc);
                ah[2] = *(const uint32_t*)(vh + (dc*16 + g)     * VSTN + jloc + 8);
                ah[3] = *(const uint32_t*)(vh + (dc*16 + g + 8) * VSTN + jloc + 8);
                al[0] = *(const uint32_t*)(vl + (dc*16 + g)     * VSTN + jloc);
                al[1] = *(const uint32_t*)(vl + (dc*16 + g + 8) * VSTN + jloc);
                al[2] = *(const uint32_t*)(vl + (dc*16 + g)     * VSTN + jloc + 8);
                al[3] = *(const uint32_t*)(vl + (dc*16 + g + 8) * VSTN + jloc + 8);

                mma_bf16(acc, ah, bh0, bh1);   // Vh * Ph
                mma_bf16(acc, ah, bl0, bl1);   // Vh * Pl
                mma_bf16(acc, al, bh0, bh1);   // Vl * Ph
            }
            __syncthreads();
        }

        // 2-way cross-half reduction via SMEM (reuse strip): red[jh][d][q]
        float* red = s;   // [2][64][8]
        *(float2*)&red[jh * 512 + (dc*16 + g)     * 8 + tg * 2] =
            make_float2(acc[0], acc[1]);
        *(float2*)&red[jh * 512 + (dc*16 + g + 8) * 8 + tg * 2] =
            make_float2(acc[2], acc[3]);
        __syncthreads();

        for (int l = tid; l < 512; l += ATHREADS) {
            const int q = l >> 6, d = l & 63;        // coalesced along d
            float v = (red[(size_t)d * 8 + q] + red[512 + (size_t)d * 8 + q])
                      * lrow[q];
            __nv_bfloat16 hb = __float2bfloat16(v);
            __nv_bfloat16 lb = __float2bfloat16(v - __bfloat162float(hb));
            const size_t go = (size_t)(b * SS + q0 + q) * DD + h * DK + d;
            Chi[go] = hb;
            Clo[go] = lb;
        }
    }
}

// ---------------------------------------------------------------------------
extern "C" void kernel_launch(void* const* d_in, const int* in_sizes, int n_in,
                              void* d_out, int out_size) {
    const float* q_in = (const float*)d_in[0];
    const float* k_in = (const float*)d_in[1];
    const float* v_in = (const float*)d_in[2];
    const float* Wq = (const float*)d_in[4];
    const float* Wk = (const float*)d_in[5];
    const float* Wv = (const float*)d_in[6];
    const float* Wo = (const float*)d_in[7];
    const float* bo = (const float*)d_in[8];

    float* out = (float*)d_out;
    float* attn_dst = nullptr;
    if ((long long)out_size >= OUT_MAIN + ATTN_ELEMS) attn_dst = out + OUT_MAIN;

    __nv_bfloat16 *pAhi, *pAlo, *pWhi, *pWlo;
    __nv_bfloat16 *pQhi, *pQlo, *pKhi, *pKlo, *pVhi, *pVlo;
    __nv_bfloat16 *pVthi, *pVtlo, *pChi, *pClo;
    cudaGetSymbolAddress((void**)&pAhi, g_Ahi);
    cudaGetSymbolAddress((void**)&pAlo, g_Alo);
    cudaGetSymbolAddress((void**)&pWhi, g_Whi);
    cudaGetSymbolAddress((void**)&pWlo, g_Wlo);
    cudaGetSymbolAddress((void**)&pQhi, g_Qhi);
    cudaGetSymbolAddress((void**)&pQlo, g_Qlo);
    cudaGetSymbolAddress((void**)&pKhi, g_Khi);
    cudaGetSymbolAddress((void**)&pKlo, g_Klo);
    cudaGetSymbolAddress((void**)&pVhi, g_Vhi);
    cudaGetSymbolAddress((void**)&pVlo, g_Vlo);
    cudaGetSymbolAddress((void**)&pVthi, g_Vthi);
    cudaGetSymbolAddress((void**)&pVtlo, g_Vtlo);
    cudaGetSymbolAddress((void**)&pChi, g_Chi);
    cudaGetSymbolAddress((void**)&pClo, g_Clo);

    // split inputs + weights to bf16 hi/lo
    {
        int n4a = (int)(ASEG / 4);
        int n4w = (int)(WSEG / 4);
        dim3 g((n4a + 255) / 256, 1, 7);
        cvt_all<<<g, 256>>>(q_in, k_in, v_in, Wq, Wk, Wv, Wo,
                            pAhi, pAlo, pWhi, pWlo, n4a, n4w);
    }

    // QKV projections -> bf16 hi/lo directly
    {
        dim3 g(DD / 128, MROWS / 128, 3);
        gemm_qkv<<<g, 256>>>(pAhi, pAlo, pWhi, pWlo,
                             pQhi, pQlo, pKhi, pKlo, pVhi, pVlo);
    }

    // V transpose to [b,h][d][s]
    {
        dim3 gt(SS / 32, DK / 32, BB * HH);
        transpose_v<<<gt, dim3(32, 8)>>>(pVhi, pVlo, pVthi, pVtlo);
    }

    // fused attention (2 blocks/SM)
    {
        const int smem_bytes = QROWS * SSTR * 4 +
                               2 * STAGE_E * 2 +
                               2 * 16 * QSB * 2 +
                               (8 + 64) * 4;
        cudaFuncSetAttribute(fused_attn,
                             cudaFuncAttributeMaxDynamicSharedMemorySize, smem_bytes);
        dim3 g(SS / QROWS, HH, BB);
        fused_attn<<<g, ATHREADS, smem_bytes>>>(pQhi, pQlo, pKhi, pKlo,
                                                pVthi, pVtlo, attn_dst,
                                                pChi, pClo);
    }

    // output projection
    {
        dim3 gg(DD / 128, MROWS / 128);
        gemm_out<<<gg, 256>>>(pChi, pClo, pWhi + 3*WSEG, pWlo + 3*WSEG, bo, out);
    }
}

// round 17
// speedup vs baseline: 1.1259x; 1.1259x over previous
#include <cuda_runtime.h>
#include <cuda_bf16.h>
#include <math.h>
#include <stdint.h>

// Problem constants
#define BB 2
#define SS 2048
#define DD 768
#define HH 12
#define DK 64
#define QROWS 16
#define JTILE 128
#define SSTRB 2072         // score strip stride (bf16 elems; 1036 words)
#define KST 72             // K tile smem stride (bf16)
#define VSTN 136           // V^T tile smem stride (bf16)
#define QSB 72             // Q smem stride (bf16)
#define ATHREADS 512
#define KSTAGE_E (128*KST*2)   // elements per K stage (hi+lo)

#define OUT_MAIN (2LL*2048*768)
#define ATTN_ELEMS (2LL*12*2048*2048)

#define MROWS (BB*SS)            // 4096
#define ASEG ((size_t)MROWS*DD)  // 3145728
#define WSEG ((size_t)DD*DD)     // 589824

// scratch
__device__ float g_attn[(size_t)ATTN_ELEMS];
__device__ __nv_bfloat16 g_Ahi[3*ASEG];
__device__ __nv_bfloat16 g_Alo[3*ASEG];
__device__ __nv_bfloat16 g_Whi[4*WSEG];
__device__ __nv_bfloat16 g_Wlo[4*WSEG];
__device__ __nv_bfloat16 g_Qhi[ASEG], g_Qlo[ASEG];
__device__ __nv_bfloat16 g_Khi[ASEG], g_Klo[ASEG];
__device__ __nv_bfloat16 g_Vhi[ASEG], g_Vlo[ASEG];
__device__ __nv_bfloat16 g_Vthi[ASEG], g_Vtlo[ASEG];
__device__ __nv_bfloat16 g_Chi[ASEG], g_Clo[ASEG];

// ===================== helpers ==============================================
__device__ __forceinline__ void split2(float a, float b, uint32_t& hi, uint32_t& lo) {
    __nv_bfloat162 h = __floats2bfloat162_rn(a, b);
    float la = a - __bfloat162float(__low2bfloat16(h));
    float lb = b - __bfloat162float(__high2bfloat16(h));
    __nv_bfloat162 l = __floats2bfloat162_rn(la, lb);
    hi = *(uint32_t*)&h;
    lo = *(uint32_t*)&l;
}

__device__ __forceinline__ void mma_bf16(float* c, const uint32_t* a,
                                         uint32_t b0, uint32_t b1) {
    asm volatile(
        "mma.sync.aligned.m16n8k16.row.col.f32.bf16.bf16.f32 "
        "{%0,%1,%2,%3}, {%4,%5,%6,%7}, {%8,%9}, {%0,%1,%2,%3};"
        : "+f"(c[0]), "+f"(c[1]), "+f"(c[2]), "+f"(c[3])
        : "r"(a[0]), "r"(a[1]), "r"(a[2]), "r"(a[3]), "r"(b0), "r"(b1));
}

__device__ __forceinline__ uint32_t smem_u32(const void* p) {
    return (uint32_t)__cvta_generic_to_shared(p);
}
#define CP16(dst, src) \
    asm volatile("cp.async.cg.shared.global [%0], [%1], 16;" \
                 :: "r"(dst), "l"(src) : "memory")
#define CPCOMMIT() asm volatile("cp.async.commit_group;" ::: "memory")
#define CPWAIT(n)  asm volatile("cp.async.wait_group %0;" :: "n"(n) : "memory")

// ===================== fp32 -> bf16 hi/lo split (7 segments) ================
__global__ void cvt_all(const float* __restrict__ x0, const float* __restrict__ x1,
                        const float* __restrict__ x2,
                        const float* __restrict__ w0, const float* __restrict__ w1,
                        const float* __restrict__ w2, const float* __restrict__ w3,
                        __nv_bfloat16* __restrict__ ahi, __nv_bfloat16* __restrict__ alo,
                        __nv_bfloat16* __restrict__ whi, __nv_bfloat16* __restrict__ wlo,
                        int n4a, int n4w) {
    const int z = blockIdx.z;
    const float* x;
    __nv_bfloat16 *hi, *lo;
    int n4;
    if (z < 3) {
        x = (z == 0) ? x0 : (z == 1) ? x1 : x2;
        hi = ahi + (size_t)z * (size_t)n4a * 4;
        lo = alo + (size_t)z * (size_t)n4a * 4;
        n4 = n4a;
    } else {
        const int w = z - 3;
        x = (w == 0) ? w0 : (w == 1) ? w1 : (w == 2) ? w2 : w3;
        hi = whi + (size_t)w * (size_t)n4w * 4;
        lo = wlo + (size_t)w * (size_t)n4w * 4;
        n4 = n4w;
    }
    int i = blockIdx.x * blockDim.x + threadIdx.x;
    if (i >= n4) return;
    float4 v = ((const float4*)x)[i];
    uint32_t h01, l01, h23, l23;
    split2(v.x, v.y, h01, l01);
    split2(v.z, v.w, h23, l23);
    ((uint32_t*)hi)[i*2]     = h01;
    ((uint32_t*)hi)[i*2 + 1] = h23;
    ((uint32_t*)lo)[i*2]     = l01;
    ((uint32_t*)lo)[i*2 + 1] = l23;
}

// ===================== shared GEMM core (cp.async 2-stage) ==================
#define TST 40
#define GST_E (128*TST)

__device__ __forceinline__ void gemm_core(
        const __nv_bfloat16* __restrict__ Ah, const __nv_bfloat16* __restrict__ Al,
        const __nv_bfloat16* __restrict__ Wh, const __nv_bfloat16* __restrict__ Wl,
        int bm, int bn, float acc[2][8][4]) {
    __shared__ __nv_bfloat16 sbuf[2][4][GST_E];

    const int tid  = threadIdx.x;
    const int lane = tid & 31;
    const int wid  = tid >> 5;
    const int wm   = wid >> 1;
    const int wn   = wid & 1;
    const int g    = lane >> 2;
    const int tg   = lane & 3;

    const int lr = tid >> 2;
    const int lc = (tid & 3) * 8;

    const __nv_bfloat16* gsrc[4];
    gsrc[0] = Ah + (size_t)bm * DD;
    gsrc[1] = Al + (size_t)bm * DD;
    gsrc[2] = Wh + (size_t)bn * DD;
    gsrc[3] = Wl + (size_t)bn * DD;

    auto issue = [&](int st, int k0) {
#pragma unroll
        for (int a = 0; a < 4; a++) {
            const __nv_bfloat16* gp = gsrc[a] + k0 + lc;
            __nv_bfloat16* sp = sbuf[st][a];
            CP16(smem_u32(sp + lr * TST + lc),        gp + (size_t)lr * DD);
            CP16(smem_u32(sp + (lr + 64) * TST + lc), gp + (size_t)(lr + 64) * DD);
        }
    };

    issue(0, 0);
    CPCOMMIT();

    for (int k0 = 0; k0 < DD; k0 += 32) {
        const int st = (k0 >> 5) & 1;
        if (k0 + 32 < DD) { issue(st ^ 1, k0 + 32); CPCOMMIT(); CPWAIT(1); }
        else              { CPWAIT(0); }
        __syncthreads();

        const __nv_bfloat16* sAh = sbuf[st][0];
        const __nv_bfloat16* sAl = sbuf[st][1];
        const __nv_bfloat16* sWh = sbuf[st][2];
        const __nv_bfloat16* sWl = sbuf[st][3];

#pragma unroll
        for (int kk = 0; kk < 32; kk += 16) {
            uint32_t ah[2][4], al[2][4];
#pragma unroll
            for (int mi = 0; mi < 2; mi++) {
                const int ar = wm*32 + mi*16;
                ah[mi][0] = *(const uint32_t*)(sAh + (ar+g)   * TST + kk + tg*2);
                ah[mi][1] = *(const uint32_t*)(sAh + (ar+g+8) * TST + kk + tg*2);
                ah[mi][2] = *(const uint32_t*)(sAh + (ar+g)   * TST + kk + tg*2 + 8);
                ah[mi][3] = *(const uint32_t*)(sAh + (ar+g+8) * TST + kk + tg*2 + 8);
                al[mi][0] = *(const uint32_t*)(sAl + (ar+g)   * TST + kk + tg*2);
                al[mi][1] = *(const uint32_t*)(sAl + (ar+g+8) * TST + kk + tg*2);
                al[mi][2] = *(const uint32_t*)(sAl + (ar+g)   * TST + kk + tg*2 + 8);
                al[mi][3] = *(const uint32_t*)(sAl + (ar+g+8) * TST + kk + tg*2 + 8);
            }
            uint32_t bh[8][2], bl[8][2];
#pragma unroll
            for (int ni = 0; ni < 8; ni++) {
                const int nr = wn*64 + ni*8 + g;
                bh[ni][0] = *(const uint32_t*)(sWh + nr * TST + kk + tg*2);
                bh[ni][1] = *(const uint32_t*)(sWh + nr * TST + kk + tg*2 + 8);
                bl[ni][0] = *(const uint32_t*)(sWl + nr * TST + kk + tg*2);
                bl[ni][1] = *(const uint32_t*)(sWl + nr * TST + kk + tg*2 + 8);
            }
#pragma unroll
            for (int ni = 0; ni < 8; ni++)
#pragma unroll
                for (int mi = 0; mi < 2; mi++)
                    mma_bf16(acc[mi][ni], ah[mi], bh[ni][0], bh[ni][1]);
#pragma unroll
            for (int ni = 0; ni < 8; ni++)
#pragma unroll
                for (int mi = 0; mi < 2; mi++)
                    mma_bf16(acc[mi][ni], ah[mi], bl[ni][0], bl[ni][1]);
#pragma unroll
            for (int ni = 0; ni < 8; ni++)
#pragma unroll
                for (int mi = 0; mi < 2; mi++)
                    mma_bf16(acc[mi][ni], al[mi], bh[ni][0], bh[ni][1]);
        }
        __syncthreads();
    }
}

__global__ __launch_bounds__(256) void gemm_qkv(
        const __nv_bfloat16* __restrict__ Ahi, const __nv_bfloat16* __restrict__ Alo,
        const __nv_bfloat16* __restrict__ Whi, const __nv_bfloat16* __restrict__ Wlo,
        __nv_bfloat16* H0, __nv_bfloat16* L0,
        __nv_bfloat16* H1, __nv_bfloat16* L1,
        __nv_bfloat16* H2, __nv_bfloat16* L2) {
    const int z = blockIdx.z;
    const __nv_bfloat16* Ah = Ahi + (size_t)z * ASEG;
    const __nv_bfloat16* Al = Alo + (size_t)z * ASEG;
    const __nv_bfloat16* Wh = Whi + (size_t)z * WSEG;
    const __nv_bfloat16* Wl = Wlo + (size_t)z * WSEG;
    __nv_bfloat16* Ho = (z == 0) ? H0 : (z == 1) ? H1 : H2;
    __nv_bfloat16* Lo = (z == 0) ? L0 : (z == 1) ? L1 : L2;
    const int bm = blockIdx.y * 128, bn = blockIdx.x * 128;

    float acc[2][8][4];
#pragma unroll
    for (int mi = 0; mi < 2; mi++)
#pragma unroll
        for (int ni = 0; ni < 8; ni++)
#pragma unroll
            for (int r = 0; r < 4; r++) acc[mi][ni][r] = 0.f;

    gemm_core(Ah, Al, Wh, Wl, bm, bn, acc);

    const int lane = threadIdx.x & 31;
    const int wid  = threadIdx.x >> 5;
    const int wm = wid >> 1, wn = wid & 1;
    const int g = lane >> 2, tg = lane & 3;
#pragma unroll
    for (int mi = 0; mi < 2; mi++) {
        const int row0 = bm + wm*32 + mi*16 + g;
#pragma unroll
        for (int ni = 0; ni < 8; ni++) {
            const int col = bn + wn*64 + ni*8 + tg*2;
            uint32_t h0, l0, h1, l1;
            split2(acc[mi][ni][0], acc[mi][ni][1], h0, l0);
            split2(acc[mi][ni][2], acc[mi][ni][3], h1, l1);
            *(uint32_t*)(Ho + (size_t)row0 * DD + col)     = h0;
            *(uint32_t*)(Lo + (size_t)row0 * DD + col)     = l0;
            *(uint32_t*)(Ho + (size_t)(row0+8) * DD + col) = h1;
            *(uint32_t*)(Lo + (size_t)(row0+8) * DD + col) = l1;
        }
    }
}

__global__ __launch_bounds__(256) void gemm_out(
        const __nv_bfloat16* __restrict__ Ahi, const __nv_bfloat16* __restrict__ Alo,
        const __nv_bfloat16* __restrict__ Whi, const __nv_bfloat16* __restrict__ Wlo,
        const float* __restrict__ bias, float* __restrict__ C) {
    const int bm = blockIdx.y * 128, bn = blockIdx.x * 128;
    float acc[2][8][4];
#pragma unroll
    for (int mi = 0; mi < 2; mi++)
#pragma unroll
        for (int ni = 0; ni < 8; ni++)
#pragma unroll
            for (int r = 0; r < 4; r++) acc[mi][ni][r] = 0.f;

    gemm_core(Ahi, Alo, Whi, Wlo, bm, bn, acc);

    const int lane = threadIdx.x & 31;
    const int wid  = threadIdx.x >> 5;
    const int wm = wid >> 1, wn = wid & 1;
    const int g = lane >> 2, tg = lane & 3;
#pragma unroll
    for (int mi = 0; mi < 2; mi++) {
        const int row0 = bm + wm*32 + mi*16 + g;
#pragma unroll
        for (int ni = 0; ni < 8; ni++) {
            const int col = bn + wn*64 + ni*8 + tg*2;
            float b0v = bias[col], b1v = bias[col+1];
            float2 v0 = {acc[mi][ni][0] + b0v, acc[mi][ni][1] + b1v};
            float2 v1 = {acc[mi][ni][2] + b0v, acc[mi][ni][3] + b1v};
            *(float2*)(C + (size_t)row0 * DD + col)     = v0;
            *(float2*)(C + (size_t)(row0+8) * DD + col) = v1;
        }
    }
}

// ===================== V transpose: [b,s][h,d] -> [b,h][d][s] ==============
__global__ void transpose_v(const __nv_bfloat16* __restrict__ Vhi,
                            const __nv_bfloat16* __restrict__ Vlo,
                            __nv_bfloat16* __restrict__ Vthi,
                            __nv_bfloat16* __restrict__ Vtlo) {
    __shared__ uint16_t th[32][33], tl[32][33];
    const int b = blockIdx.z / HH, h = blockIdx.z % HH;
    const int s0 = blockIdx.x * 32, d0 = blockIdx.y * 32;
    const int tx = threadIdx.x, ty = threadIdx.y;
#pragma unroll
    for (int i = 0; i < 4; i++) {
        const int srow = ty + i * 8;
        const size_t gi = (size_t)(b * SS + s0 + srow) * DD + h * DK + d0 + tx;
        th[srow][tx] = ((const uint16_t*)Vhi)[gi];
        tl[srow][tx] = ((const uint16_t*)Vlo)[gi];
    }
    __syncthreads();
#pragma unroll
    for (int i = 0; i < 4; i++) {
        const int drow = ty + i * 8;
        const size_t go = ((size_t)(b * HH + h) * DK + d0 + drow) * SS + s0 + tx;
        ((uint16_t*)Vthi)[go] = th[tx][drow];
        ((uint16_t*)Vtlo)[go] = tl[tx][drow];
    }
}

// ===================== fused attention (bf16 pre-split strip) ===============
__global__ __launch_bounds__(ATHREADS) void fused_attn(
        const __nv_bfloat16* __restrict__ Qhi, const __nv_bfloat16* __restrict__ Qlo,
        const __nv_bfloat16* __restrict__ Khi, const __nv_bfloat16* __restrict__ Klo,
        const __nv_bfloat16* __restrict__ Vthi, const __nv_bfloat16* __restrict__ Vtlo,
        float* __restrict__ attn,
        __nv_bfloat16* __restrict__ Chi, __nv_bfloat16* __restrict__ Clo) {
    const int qt = gridDim.x - 1 - blockIdx.x;
    const int h  = blockIdx.y;
    const int b  = blockIdx.z;
    const int q0 = qt * QROWS;
    const int tid = threadIdx.x;
    const int wid  = tid >> 5;
    const int lane = tid & 31;
    const int g    = lane >> 2;
    const int tg   = lane & 3;

    extern __shared__ float sm[];
    __nv_bfloat16* shi = (__nv_bfloat16*)sm;                       // [16][SSTRB]
    __nv_bfloat16* slo = shi + QROWS * SSTRB;                      // [16][SSTRB]
    __nv_bfloat16* kbuf = slo + QROWS * SSTRB;                     // 2 stages
    __nv_bfloat16* qsh = kbuf + 2 * KSTAGE_E;                      // 16*QSB
    __nv_bfloat16* qsl = qsh + QROWS * QSB;                        // 16*QSB
    float* lrow = (float*)(qsl + QROWS * QSB);                     // [16]
    float* wsum = lrow + 16;                                       // [16][16]

    // stage Q hi/lo
    for (int l = tid; l < QROWS * 8; l += ATHREADS) {
        const int r = l >> 3, c8 = (l & 7) * 8;
        const size_t gi = (size_t)(b * SS + q0 + r) * DD + h * DK + c8;
        *(uint4*)(qsh + r * QSB + c8) = *(const uint4*)(Qhi + gi);
        *(uint4*)(qsl + r * QSB + c8) = *(const uint4*)(Qlo + gi);
    }
    __syncthreads();

    uint32_t qh[4][4], ql[4][4];
#pragma unroll
    for (int ks = 0; ks < 4; ks++) {
        const int c0 = ks * 16 + tg * 2;
        qh[ks][0] = *(const uint32_t*)(qsh + g * QSB + c0);
        qh[ks][1] = *(const uint32_t*)(qsh + (g + 8) * QSB + c0);
        qh[ks][2] = *(const uint32_t*)(qsh + g * QSB + c0 + 8);
        qh[ks][3] = *(const uint32_t*)(qsh + (g + 8) * QSB + c0 + 8);
        ql[ks][0] = *(const uint32_t*)(qsl + g * QSB + c0);
        ql[ks][1] = *(const uint32_t*)(qsl + (g + 8) * QSB + c0);
        ql[ks][2] = *(const uint32_t*)(qsl + g * QSB + c0 + 8);
        ql[ks][3] = *(const uint32_t*)(qsl + (g + 8) * QSB + c0 + 8);
    }

    const int ntile = (q0 + QROWS + JTILE - 1) / JTILE;
    const int jlim  = ntile * JTILE;

    // ---- Phase 1: scores -> exp -> pre-split bf16 strip, row sums ----
    float rs0 = 0.f, rs1 = 0.f;
    {
        auto issueK = [&](int st, int t) {
            const int j0 = t * JTILE;
            __nv_bfloat16* kh = kbuf + st * KSTAGE_E;
            __nv_bfloat16* kl = kh + 128 * KST;
#pragma unroll
            for (int it = 0; it < 2; it++) {
                const int l = tid + it * ATHREADS;
                const int jr = l >> 3, c8 = (l & 7) * 8;
                const size_t gi = (size_t)(b * SS + j0 + jr) * DD + h * DK + c8;
                CP16(smem_u32(kh + jr * KST + c8), Khi + gi);
                CP16(smem_u32(kl + jr * KST + c8), Klo + gi);
            }
        };

        issueK(0, 0);
        CPCOMMIT();
        for (int t = 0; t < ntile; t++) {
            if (t + 1 < ntile) { issueK((t + 1) & 1, t + 1); CPCOMMIT(); CPWAIT(1); }
            else               { CPWAIT(0); }
            __syncthreads();

            const __nv_bfloat16* kh = kbuf + (t & 1) * KSTAGE_E;
            const __nv_bfloat16* kl = kh + 128 * KST;
            const int j0 = t * JTILE;
            const int n0 = wid * 8;
            float c[4] = {0.f, 0.f, 0.f, 0.f};
#pragma unroll
            for (int ks = 0; ks < 4; ks++) {
                const int ko = ks * 16 + tg * 2;
                uint32_t bh0 = *(const uint32_t*)(kh + (n0 + g) * KST + ko);
                uint32_t bh1 = *(const uint32_t*)(kh + (n0 + g) * KST + ko + 8);
                uint32_t bl0 = *(const uint32_t*)(kl + (n0 + g) * KST + ko);
                uint32_t bl1 = *(const uint32_t*)(kl + (n0 + g) * KST + ko + 8);
                mma_bf16(c, qh[ks], bh0, bh1);
                mma_bf16(c, qh[ks], bl0, bl1);
                mma_bf16(c, ql[ks], bh0, bh1);
            }
            const int gj = j0 + n0 + tg * 2;
            const int r0 = q0 + g, r1 = q0 + g + 8;
            float e00 = (gj     <= r0) ? __expf(c[0] * 0.125f) : 0.f;
            float e01 = (gj + 1 <= r0) ? __expf(c[1] * 0.125f) : 0.f;
            float e10 = (gj     <= r1) ? __expf(c[2] * 0.125f) : 0.f;
            float e11 = (gj + 1 <= r1) ? __expf(c[3] * 0.125f) : 0.f;
            uint32_t h0, l0, h1, l1;
            split2(e00, e01, h0, l0);
            split2(e10, e11, h1, l1);
            *(uint32_t*)(shi + g * SSTRB + gj)       = h0;
            *(uint32_t*)(slo + g * SSTRB + gj)       = l0;
            *(uint32_t*)(shi + (g + 8) * SSTRB + gj) = h1;
            *(uint32_t*)(slo + (g + 8) * SSTRB + gj) = l1;
            rs0 += e00 + e01;
            rs1 += e10 + e11;
            __syncthreads();
        }
    }

    // ---- Phase 2: tiny cross-lane/warp sum reduce ----
    rs0 += __shfl_xor_sync(0xffffffffu, rs0, 1);
    rs0 += __shfl_xor_sync(0xffffffffu, rs0, 2);
    rs1 += __shfl_xor_sync(0xffffffffu, rs1, 1);
    rs1 += __shfl_xor_sync(0xffffffffu, rs1, 2);
    if (tg == 0) {
        wsum[wid * 16 + g]     = rs0;
        wsum[wid * 16 + 8 + g] = rs1;
    }
    __syncthreads();
    if (tid < 16) {
        float sum = 0.f;
#pragma unroll
        for (int w = 0; w < 16; w++) sum += wsum[w * 16 + tid];
        lrow[tid] = 1.0f / sum;
    }
    __syncthreads();

    // ---- Phase 3: zero-fill tail of weight rows (j >= jlim) ----
    if (attn) {
        const float4 zz = {0.f, 0.f, 0.f, 0.f};
        const int jlim4 = jlim >> 2;
        for (int r = 0; r < QROWS; r++) {
            float4* arow = (float4*)(attn +
                (((size_t)(b * HH + h) * SS) + q0 + r) * SS);
            for (int j = jlim4 + tid; j < SS/4; j += ATHREADS)
                __stcs(&arow[j], zz);
        }
    }

    // ---- Phase 4: P @ V; P fragments loaded directly from bf16 strip ----
    {
        const size_t vtbase = (size_t)(b * HH + h) * DK * SS;
        const size_t abase  = ((size_t)(b * HH + h) * SS + q0) * SS;
        auto issueV = [&](int st, int t) {
            const int j0 = t * JTILE;
            __nv_bfloat16* vh = kbuf + st * KSTAGE_E;
            __nv_bfloat16* vl = vh + 64 * VSTN;
#pragma unroll
            for (int it = 0; it < 2; it++) {
                const int l = tid + it * ATHREADS;
                const int d = l >> 4, j8 = (l & 15) * 8;
                const size_t gi = vtbase + (size_t)d * SS + j0 + j8;
                CP16(smem_u32(vh + d * VSTN + j8), Vthi + gi);
                CP16(smem_u32(vl + d * VSTN + j8), Vtlo + gi);
            }
        };

        const int jsl = wid & 7;
        const int dh  = wid >> 3;
        const float inv0 = lrow[g];
        const float inv1 = lrow[g + 8];

        float acc[4][4];
#pragma unroll
        for (int nf = 0; nf < 4; nf++)
#pragma unroll
            for (int r = 0; r < 4; r++) acc[nf][r] = 0.f;

        issueV(0, 0);
        CPCOMMIT();
        for (int t = 0; t < ntile; t++) {
            if (t + 1 < ntile) { issueV((t + 1) & 1, t + 1); CPCOMMIT(); CPWAIT(1); }
            else               { CPWAIT(0); }
            __syncthreads();

            const __nv_bfloat16* vh = kbuf + (t & 1) * KSTAGE_E;
            const __nv_bfloat16* vl = vh + 64 * VSTN;
            const int j0 = t * JTILE;
            const int c0 = j0 + jsl * 16 + tg * 2;

            // P fragments directly from pre-split strip
            uint32_t ah[4], al[4];
            ah[0] = *(const uint32_t*)(shi + g * SSTRB + c0);
            ah[1] = *(const uint32_t*)(shi + (g + 8) * SSTRB + c0);
            ah[2] = *(const uint32_t*)(shi + g * SSTRB + c0 + 8);
            ah[3] = *(const uint32_t*)(shi + (g + 8) * SSTRB + c0 + 8);
            al[0] = *(const uint32_t*)(slo + g * SSTRB + c0);
            al[1] = *(const uint32_t*)(slo + (g + 8) * SSTRB + c0);
            al[2] = *(const uint32_t*)(slo + g * SSTRB + c0 + 8);
            al[3] = *(const uint32_t*)(slo + (g + 8) * SSTRB + c0 + 8);

            // fused weight write (reconstruct p = hi + lo)
            if (attn && dh == 0) {
                float2 h00 = __bfloat1622float2(*(__nv_bfloat162*)&ah[0]);
                float2 l00 = __bfloat1622float2(*(__nv_bfloat162*)&al[0]);
                float2 h10 = __bfloat1622float2(*(__nv_bfloat162*)&ah[1]);
                float2 l10 = __bfloat1622float2(*(__nv_bfloat162*)&al[1]);
                float2 h01 = __bfloat1622float2(*(__nv_bfloat162*)&ah[2]);
                float2 l01 = __bfloat1622float2(*(__nv_bfloat162*)&al[2]);
                float2 h11 = __bfloat1622float2(*(__nv_bfloat162*)&ah[3]);
                float2 l11 = __bfloat1622float2(*(__nv_bfloat162*)&al[3]);
                __stcs((float2*)(attn + abase + (size_t)g * SS + c0),
                       make_float2((h00.x + l00.x) * inv0, (h00.y + l00.y) * inv0));
                __stcs((float2*)(attn + abase + (size_t)g * SS + c0 + 8),
                       make_float2((h01.x + l01.x) * inv0, (h01.y + l01.y) * inv0));
                __stcs((float2*)(attn + abase + (size_t)(g + 8) * SS + c0),
                       make_float2((h10.x + l10.x) * inv1, (h10.y + l10.y) * inv1));
                __stcs((float2*)(attn + abase + (size_t)(g + 8) * SS + c0 + 8),
                       make_float2((h11.x + l11.x) * inv1, (h11.y + l11.y) * inv1));
            }

            const int jloc = jsl * 16 + tg * 2;
#pragma unroll
            for (int nf = 0; nf < 4; nf++) {
                const int d = dh * 32 + nf * 8 + g;
                uint32_t bh0 = *(const uint32_t*)(vh + d * VSTN + jloc);
                uint32_t bh1 = *(const uint32_t*)(vh + d * VSTN + jloc + 8);
                uint32_t bl0 = *(const uint32_t*)(vl + d * VSTN + jloc);
                uint32_t bl1 = *(const uint32_t*)(vl + d * VSTN + jloc + 8);
                mma_bf16(acc[nf], ah, bh0, bh1);
                mma_bf16(acc[nf], ah, bl0, bl1);
                mma_bf16(acc[nf], al, bh0, bh1);
            }
            __syncthreads();
        }

        // 8-way cross-warp reduction via SMEM (reuse strip as fp32)
        float* red = (float*)shi;   // [8][16][64]
#pragma unroll
        for (int nf = 0; nf < 4; nf++) {
            const int col = dh * 32 + nf * 8 + tg * 2;
            *(float2*)&red[jsl * 1024 + g * 64 + col] =
                make_float2(acc[nf][0], acc[nf][1]);
            *(float2*)&red[jsl * 1024 + (g + 8) * 64 + col] =
                make_float2(acc[nf][2], acc[nf][3]);
        }
        __syncthreads();

        for (int l = tid; l < 512; l += ATHREADS) {
            const int q = l >> 5, dp = (l & 31) * 2;
            float v0 = 0.f, v1 = 0.f;
#pragma unroll
            for (int w = 0; w < 8; w++) {
                v0 += red[w * 1024 + q * 64 + dp];
                v1 += red[w * 1024 + q * 64 + dp + 1];
            }
            const float inv = lrow[q];
            uint32_t hi32, lo32;
            split2(v0 * inv, v1 * inv, hi32, lo32);
            const size_t go = (size_t)(b * SS + q0 + q) * DD + h * DK + dp;
            *(uint32_t*)(Chi + go) = hi32;
            *(uint32_t*)(Clo + go) = lo32;
        }
    }
}

// ---------------------------------------------------------------------------
extern "C" void kernel_launch(void* const* d_in, const int* in_sizes, int n_in,
                              void* d_out, int out_size) {
    const float* q_in = (const float*)d_in[0];
    const float* k_in = (const float*)d_in[1];
    const float* v_in = (const float*)d_in[2];
    const float* Wq = (const float*)d_in[4];
    const float* Wk = (const float*)d_in[5];
    const float* Wv = (const float*)d_in[6];
    const float* Wo = (const float*)d_in[7];
    const float* bo = (const float*)d_in[8];

    float* out = (float*)d_out;
    float* attn_dst = nullptr;
    if ((long long)out_size >= OUT_MAIN + ATTN_ELEMS) attn_dst = out + OUT_MAIN;

    __nv_bfloat16 *pAhi, *pAlo, *pWhi, *pWlo;
    __nv_bfloat16 *pQhi, *pQlo, *pKhi, *pKlo, *pVhi, *pVlo;
    __nv_bfloat16 *pVthi, *pVtlo, *pChi, *pClo;
    cudaGetSymbolAddress((void**)&pAhi, g_Ahi);
    cudaGetSymbolAddress((void**)&pAlo, g_Alo);
    cudaGetSymbolAddress((void**)&pWhi, g_Whi);
    cudaGetSymbolAddress((void**)&pWlo, g_Wlo);
    cudaGetSymbolAddress((void**)&pQhi, g_Qhi);
    cudaGetSymbolAddress((void**)&pQlo, g_Qlo);
    cudaGetSymbolAddress((void**)&pKhi, g_Khi);
    cudaGetSymbolAddress((void**)&pKlo, g_Klo);
    cudaGetSymbolAddress((void**)&pVhi, g_Vhi);
    cudaGetSymbolAddress((void**)&pVlo, g_Vlo);
    cudaGetSymbolAddress((void**)&pVthi, g_Vthi);
    cudaGetSymbolAddress((void**)&pVtlo, g_Vtlo);
    cudaGetSymbolAddress((void**)&pChi, g_Chi);
    cudaGetSymbolAddress((void**)&pClo, g_Clo);

    // split inputs + weights to bf16 hi/lo (single launch)
    {
        int n4a = (int)(ASEG / 4);
        int n4w = (int)(WSEG / 4);
        dim3 g((n4a + 255) / 256, 1, 7);
        cvt_all<<<g, 256>>>(q_in, k_in, v_in, Wq, Wk, Wv, Wo,
                            pAhi, pAlo, pWhi, pWlo, n4a, n4w);
    }

    // QKV projections -> bf16 hi/lo directly
    {
        dim3 g(DD / 128, MROWS / 128, 3);
        gemm_qkv<<<g, 256>>>(pAhi, pAlo, pWhi, pWlo,
                             pQhi, pQlo, pKhi, pKlo, pVhi, pVlo);
    }

    // V transpose to [b,h][d][s]
    {
        dim3 gt(SS / 32, DK / 32, BB * HH);
        transpose_v<<<gt, dim3(32, 8)>>>(pVhi, pVlo, pVthi, pVtlo);
    }

    // fused attention
    {
        const int smem_bytes = 2 * QROWS * SSTRB * 2 +
                               2 * KSTAGE_E * 2 +
                               2 * QROWS * QSB * 2 +
                               (16 + 256) * 4;
        cudaFuncSetAttribute(fused_attn,
                             cudaFuncAttributeMaxDynamicSharedMemorySize, smem_bytes);
        dim3 g(SS / QROWS, HH, BB);
        fused_attn<<<g, ATHREADS, smem_bytes>>>(pQhi, pQlo, pKhi, pKlo,
                                                pVthi, pVtlo, attn_dst,
                                                pChi, pClo);
    }

    // output projection
    {
        dim3 gg(DD / 128, MROWS / 128);
        gemm_out<<<gg, 256>>>(pChi, pClo, pWhi + 3*WSEG, pWlo + 3*WSEG, bo, out);
    }
}